// round 10
// baseline (speedup 1.0000x reference)
#include <cuda_runtime.h>
#include <cstdint>

#define N_PTS   4096
#define DIM     128
#define TOPK    4

// ---------------- global scratch ----------------
__device__ float Z_buf[2 * N_PTS * DIM];                 // x @ W  (4 MB)
__device__ unsigned long long Top5x[2 * N_PTS * 16];     // per row: [half][8] exact u64 keys (5 used)

#define BUBBLE5(k)                                            \
    { float _t, _k = (k);                                     \
      _t = fminf(s0, _k); _k = fmaxf(s0, _k); s0 = _t;        \
      _t = fminf(s1, _k); _k = fmaxf(s1, _k); s1 = _t;        \
      _t = fminf(s2, _k); _k = fmaxf(s2, _k); s2 = _t;        \
      _t = fminf(s3, _k); _k = fmaxf(s3, _k); s3 = _t;        \
      s4 = fminf(s4, _k); }

#define SWP(a,b) { unsigned long long _t; if (a > b) { _t = a; a = b; b = _t; } }

// ---------------- kernel 1: interleaved scan / GEMM roles ----------------
// even blocks: top-5 scan per (32-row group, 2048-cand half), exact u64 output
// odd  blocks: Z = x @ W for (32-row group, 64-col half)

#define K1_THREADS 512
#define SB_WARPS   16
#define HALF_C     (N_PTS / 2)              // 2048
#define SB_SLICE   (HALF_C / SB_WARPS)      // 128
#define SB_L1      32
#define COLH       64                       // GEMM cols per block

#define TREEMERGE()                                                        \
    _Pragma("unroll")                                                      \
    for (int step = 8; step >= 1; step >>= 1) {                            \
        if (warp >= step && warp < 2 * step) {                             \
            float* m = m_s + ((warp - step) * 32 + lane) * 5;              \
            m[0] = s0; m[1] = s1; m[2] = s2; m[3] = s3; m[4] = s4;         \
        }                                                                  \
        __syncthreads();                                                   \
        if (warp < step) {                                                 \
            const float* m = m_s + (warp * 32 + lane) * 5;                 \
            BUBBLE5(m[0]); BUBBLE5(m[1]); BUBBLE5(m[2]);                   \
            BUBBLE5(m[3]); BUBBLE5(m[4]);                                  \
        }                                                                  \
        __syncthreads();                                                   \
    }

__global__ void __launch_bounds__(K1_THREADS, 3)
scan_and_gemm(const float* __restrict__ pos,
              const float* __restrict__ x,
              const float* __restrict__ W)
{
    extern __shared__ float smem[];
    const int tid  = threadIdx.x;
    const int warp = tid >> 5;
    const int lane = tid & 31;

    if ((blockIdx.x & 1) == 0) {
        // ================= SCAN ROLE =================
        float4* pos_s  = (float4*)smem;                    // [2048] .w = -0.5|p|^2
        float*  m_s    = (float*)(pos_s + HALF_C);         // [8*32*5]
        float*  base_s = m_s + 8 * 32 * 5;                 // [32*5]
        float*  tau_s  = base_s + 32 * 5;                  // [32]

        const int sid  = blockIdx.x >> 1;                  // 0..511
        const int rg   = sid >> 1;
        const int half = sid & 1;
        const int r0   = rg * 32;
        const int b    = r0 >> 12;
        const int n0   = r0 & (N_PTS - 1);
        const int cb   = half * HALF_C;

        const float* pb = pos + ((size_t)b * N_PTS + cb) * 3;
        const float4* pb4 = (const float4*)pb;
        for (int g = tid; g < HALF_C / 4; g += K1_THREADS) {
            float4 a = pb4[3*g + 0];
            float4 c = pb4[3*g + 1];
            float4 d = pb4[3*g + 2];
            float4 q;
            q.x = a.x; q.y = a.y; q.z = a.z;
            q.w = -0.5f * fmaf(q.z, q.z, fmaf(q.y, q.y, q.x * q.x));
            pos_s[4*g + 0] = q;
            q.x = a.w; q.y = c.x; q.z = c.y;
            q.w = -0.5f * fmaf(q.z, q.z, fmaf(q.y, q.y, q.x * q.x));
            pos_s[4*g + 1] = q;
            q.x = c.z; q.y = c.w; q.z = d.x;
            q.w = -0.5f * fmaf(q.z, q.z, fmaf(q.y, q.y, q.x * q.x));
            pos_s[4*g + 2] = q;
            q.x = d.y; q.y = d.z; q.z = d.w;
            q.w = -0.5f * fmaf(q.z, q.z, fmaf(q.y, q.y, q.x * q.x));
            pos_s[4*g + 3] = q;
        }
        __syncthreads();

        const float* pr = pos + ((size_t)b * N_PTS + n0 + lane) * 3;
        float Px = __ldg(pr), Py = __ldg(pr + 1), Pz = __ldg(pr + 2);
        const float Pw2 = fmaf(Pz, Pz, fmaf(Py, Py, Px * Px));

        const float INF = __int_as_float(0x7f800000);
        float s0 = INF, s1 = INF, s2 = INF, s3 = INF, s4 = INF;

        const int base = warp * SB_SLICE;

        // phase 1: unconditional (32 cands/warp)
        #pragma unroll 8
        for (int jj = 0; jj < SB_L1; jj++) {
            const int j = base + jj;
            float4 q = pos_s[j];
            float t   = fmaf(Px, q.x, fmaf(Py, q.y, fmaf(Pz, q.z, q.w)));
            float d2c = fmaf(-2.0f, t, Pw2);
            float k   = __int_as_float((__float_as_int(d2c) & 0xFFFFF000) | (cb + j));
            BUBBLE5(k);
        }

        TREEMERGE();

        if (warp == 0) {
            float* bs = base_s + lane * 5;
            bs[0] = s0; bs[1] = s1; bs[2] = s2; bs[3] = s3; bs[4] = s4;
            tau_s[lane] = __int_as_float((__float_as_int(s4) & 0xFFFFF000) + 0x1000);
        }
        __syncthreads();

        const float tau = tau_s[lane];

        // phase 2: filtered
        s0 = INF; s1 = INF; s2 = INF; s3 = INF; s4 = INF;
        #pragma unroll 8
        for (int jj = SB_L1; jj < SB_SLICE; jj++) {
            const int j = base + jj;
            float4 q = pos_s[j];
            float t   = fmaf(Px, q.x, fmaf(Py, q.y, fmaf(Pz, q.z, q.w)));
            float d2c = fmaf(-2.0f, t, Pw2);
            if (d2c < tau) {
                float k = __int_as_float((__float_as_int(d2c) & 0xFFFFF000) | (cb + j));
                BUBBLE5(k);
            }
        }

        TREEMERGE();

        if (warp == 0) {
            const float* bs = base_s + lane * 5;
            BUBBLE5(bs[0]); BUBBLE5(bs[1]); BUBBLE5(bs[2]);
            BUBBLE5(bs[3]); BUBBLE5(bs[4]);

            // exact difference-form rerank of the 5 survivors (pos in smem!)
            float cand[5] = { s0, s1, s2, s3, s4 };
            unsigned long long k[5];
            #pragma unroll
            for (int i = 0; i < 5; i++) {
                int jg = __float_as_int(cand[i]) & 0xFFF;   // within-batch index
                float4 q = pos_s[jg - cb];
                float dx = Px - q.x, dy = Py - q.y, dz = Pz - q.z;
                float d2 = fmaf(dz, dz, fmaf(dy, dy, dx * dx));
                k[i] = ((unsigned long long)__float_as_uint(d2) << 32) | (unsigned)jg;
            }
            SWP(k[0],k[1]) SWP(k[3],k[4]) SWP(k[2],k[4]) SWP(k[2],k[3]) SWP(k[0],k[3])
            SWP(k[0],k[2]) SWP(k[1],k[4]) SWP(k[1],k[3]) SWP(k[1],k[2])

            unsigned long long* dst = Top5x + ((size_t)(r0 + lane) * 2 + half) * 8;
            dst[0] = k[0]; dst[1] = k[1]; dst[2] = k[2];
            dst[3] = k[3]; dst[4] = k[4];
        }
    } else {
        // ================= GEMM ROLE: Z[rg*32..+32][colh*64..+64] =================
        float2* W2_s = (float2*)smem;                      // [128][32] float2 = 32 KB
        float*  x_s  = (float*)(W2_s + DIM * 32);          // [32][128] = 16 KB

        const int gid  = blockIdx.x >> 1;                  // 0..511
        const int rg   = gid >> 1;
        const int colh = gid & 1;
        const int g0   = rg * 32;

        // load W half: W[d][colh*64 + 2p .. +1]  (global row-major [128][128])
        const float2* W2 = (const float2*)W;
        #pragma unroll
        for (int i = tid; i < DIM * 32; i += K1_THREADS) {
            int d = i >> 5, p = i & 31;
            W2_s[i] = __ldg(&W2[d * 64 + colh * 32 + p]);
        }
        // load x rows
        const float4* xg = (const float4*)x + (size_t)g0 * 32;
        float4* xs4 = (float4*)x_s;
        #pragma unroll
        for (int i = tid; i < 32 * 32; i += K1_THREADS) xs4[i] = __ldg(&xg[i]);
        __syncthreads();

        const int r0l = warp * 2;                          // 2 rows per warp
        const float4* ya4 = (const float4*)(x_s + (r0l + 0) * DIM);
        const float4* yb4 = (const float4*)(x_s + (r0l + 1) * DIM);

        float2 a0 = make_float2(0.f, 0.f), a1 = a0;

        #pragma unroll 8
        for (int dd = 0; dd < DIM / 4; dd++) {
            float4 ya = ya4[dd];
            float4 yb = yb4[dd];
            float2 w0 = W2_s[(4*dd + 0) * 32 + lane];
            float2 w1 = W2_s[(4*dd + 1) * 32 + lane];
            float2 w2 = W2_s[(4*dd + 2) * 32 + lane];
            float2 w3 = W2_s[(4*dd + 3) * 32 + lane];
            a0.x = fmaf(ya.x, w0.x, a0.x); a0.y = fmaf(ya.x, w0.y, a0.y);
            a1.x = fmaf(yb.x, w0.x, a1.x); a1.y = fmaf(yb.x, w0.y, a1.y);
            a0.x = fmaf(ya.y, w1.x, a0.x); a0.y = fmaf(ya.y, w1.y, a0.y);
            a1.x = fmaf(yb.y, w1.x, a1.x); a1.y = fmaf(yb.y, w1.y, a1.y);
            a0.x = fmaf(ya.z, w2.x, a0.x); a0.y = fmaf(ya.z, w2.y, a0.y);
            a1.x = fmaf(yb.z, w2.x, a1.x); a1.y = fmaf(yb.z, w2.y, a1.y);
            a0.x = fmaf(ya.w, w3.x, a0.x); a0.y = fmaf(ya.w, w3.y, a0.y);
            a1.x = fmaf(yb.w, w3.x, a1.x); a1.y = fmaf(yb.w, w3.y, a1.y);
        }

        float2* Z2 = (float2*)Z_buf;
        const size_t cofs = (size_t)colh * 32 + lane;      // float2 col index
        Z2[((size_t)(g0 + r0l + 0)) * 64 + cofs] = a0;
        Z2[((size_t)(g0 + r0l + 1)) * 64 + cofs] = a1;
    }
}

// ---------------- kernel 2: merge sorted halves, weights, gather ----------------
#define GC_THREADS 256
#define GC_WARPS   8           // one row per warp

__global__ void __launch_bounds__(GC_THREADS, 8)
finish_gather(const float* __restrict__ bias,
              float* __restrict__ out)
{
    const int tid  = threadIdx.x;
    const int warp = tid >> 5;
    const int lane = tid & 31;
    const int row  = blockIdx.x * GC_WARPS + warp;     // global row (b*4096+n)
    const int b    = row >> 12;

    // two sorted 5-lists; top-4 of union lies in the first 4 of each
    const unsigned long long* t = Top5x + (size_t)row * 16;
    unsigned long long A0 = __ldg(&t[0]),  A1 = __ldg(&t[1]),
                       A2 = __ldg(&t[2]),  A3 = __ldg(&t[3]);
    unsigned long long B0 = __ldg(&t[8]),  B1 = __ldg(&t[9]),
                       B2 = __ldg(&t[10]), B3 = __ldg(&t[11]);

    float w0,w1,w2,w3; int i0,i1,i2,i3;
    #pragma unroll
    for (int r = 0; r < TOPK; r++) {
        bool ta = A0 < B0;
        unsigned long long v = ta ? A0 : B0;
        if (ta) { A0 = A1; A1 = A2; A2 = A3; A3 = ~0ull; }
        else    { B0 = B1; B1 = B2; B2 = B3; B3 = ~0ull; }
        float d2 = __uint_as_float((unsigned)(v >> 32));
        float ww = expf(-0.5f * (d2 + 1e-8f));
        int   jj = (int)(v & 0xFFFFFFFFull);
        if      (r == 0) { w0 = ww; i0 = jj; }
        else if (r == 1) { w1 = ww; i1 = jj; }
        else if (r == 2) { w2 = ww; i2 = jj; }
        else             { w3 = ww; i3 = jj; }
    }
    float inv = 1.0f / (((w0 + w1) + w2) + w3 + 1e-8f);
    w0 *= inv; w1 *= inv; w2 *= inv; w3 *= inv;

    // gather Z rows + bias
    const float4* Z4 = (const float4*)Z_buf + (size_t)b * N_PTS * 32;
    float4 acc = __ldg(&((const float4*)bias)[lane]);
    float4 z0 = Z4[(size_t)i0 * 32 + lane];
    float4 z1 = Z4[(size_t)i1 * 32 + lane];
    float4 z2 = Z4[(size_t)i2 * 32 + lane];
    float4 z3 = Z4[(size_t)i3 * 32 + lane];
    acc.x = fmaf(w0,z0.x, fmaf(w1,z1.x, fmaf(w2,z2.x, fmaf(w3,z3.x, acc.x))));
    acc.y = fmaf(w0,z0.y, fmaf(w1,z1.y, fmaf(w2,z2.y, fmaf(w3,z3.y, acc.y))));
    acc.z = fmaf(w0,z0.z, fmaf(w1,z1.z, fmaf(w2,z2.z, fmaf(w3,z3.z, acc.z))));
    acc.w = fmaf(w0,z0.w, fmaf(w1,z1.w, fmaf(w2,z2.w, fmaf(w3,z3.w, acc.w))));
    ((float4*)out)[(size_t)row * 32 + lane] = acc;
}

extern "C" void kernel_launch(void* const* d_in, const int* in_sizes, int n_in,
                              void* d_out, int out_size)
{
    const float* x    = (const float*)d_in[0];
    const float* pos  = (const float*)d_in[1];
    const float* W    = (const float*)d_in[2];
    const float* bias = (const float*)d_in[3];
    float* out        = (float*)d_out;

    const int rows = in_sizes[1] / 3;                  // B * N = 8192

    // K1: 512 scan + 512 GEMM blocks, interleaved by parity
    const size_t smemScan = (size_t)HALF_C * 16 + 8*32*5*4 + 32*5*4 + 32*4;   // 38656
    const size_t smemGemm = (size_t)DIM * 32 * 8 + (size_t)32 * DIM * 4;      // 49152
    const size_t smem1 = smemScan > smemGemm ? smemScan : smemGemm;
    cudaFuncSetAttribute(scan_and_gemm, cudaFuncAttributeMaxDynamicSharedMemorySize, (int)smem1);
    scan_and_gemm<<<(rows / 32) * 4, K1_THREADS, smem1>>>(pos, x, W);

    // K2: merge + weights + gather
    finish_gather<<<rows / GC_WARPS, GC_THREADS>>>(bias, out);
}